// round 9
// baseline (speedup 1.0000x reference)
#include <cuda_runtime.h>
#include <cuda_fp16.h>
#include <math.h>
#include <stdint.h>

// ---------------- problem constants ----------------
#define NCH   200
#define TLEN  1024
#define MD    512
#define NB    32
#define KPAD  608          // 600 real (200ch*3taps) + 8 zeros; 9 chunks of 64 + 1 of 32

// ---------------- tiling ----------------
#define TILE_M 128
#define TILE_N 64
#define KCH    64
#define NFULL  9                   // full 64-K chunks; chunk 9 is the 32-K tail
#define NCHUNK 10
#define NSTAGE 3
#define RS     72                  // smem row stride in halfs (144B; LDSM conflict-free)
#define A_O    0
#define A_BYTES (128 * RS * 2)             // 18432
#define B_O    A_BYTES
#define B_BYTES (64 * RS * 2)              // 9216
#define STAGE_BYTES (A_BYTES + B_BYTES)    // 27648
#define SMEM_TOTAL  (NSTAGE * STAGE_BYTES) // 82944 -> 2 CTAs/SM

// ---------------- device scratch (bss) ----------------
__device__ __half g_A[4096 * KPAD];
__device__ __half g_B[(size_t)NB * TLEN * KPAD];

// ---------------- PTX helpers (baseline PTX, compute_103-safe) ----------------
__device__ __forceinline__ uint32_t s2u(const void* p) {
    uint32_t a;
    asm("{ .reg .u64 t; cvta.to.shared.u64 t, %1; cvt.u32.u64 %0, t; }" : "=r"(a) : "l"(p));
    return a;
}
#define CPASYNC16(dst, src) \
    asm volatile("cp.async.cg.shared.global [%0], [%1], 16;" :: "r"(dst), "l"(src) : "memory")
#define CP_COMMIT() asm volatile("cp.async.commit_group;" ::: "memory")
#define CP_WAIT(n)  asm volatile("cp.async.wait_group %0;" :: "n"(n) : "memory")

__device__ __forceinline__ void ldsm_x4(uint32_t* r, uint32_t addr) {
    asm volatile("ldmatrix.sync.aligned.m8n8.x4.shared.b16 {%0,%1,%2,%3}, [%4];"
        : "=r"(r[0]), "=r"(r[1]), "=r"(r[2]), "=r"(r[3]) : "r"(addr));
}
__device__ __forceinline__ void mma16816h(float* c, const uint32_t* a, const uint32_t* b) {
    asm volatile("mma.sync.aligned.m16n8k16.row.col.f32.f16.f16.f32 "
        "{%0,%1,%2,%3}, {%4,%5,%6,%7}, {%8,%9}, {%0,%1,%2,%3};"
        : "+f"(c[0]), "+f"(c[1]), "+f"(c[2]), "+f"(c[3])
        : "r"(a[0]), "r"(a[1]), "r"(a[2]), "r"(a[3]), "r"(b[0]), "r"(b[1]));
}

// exact-erf GELU via A&S 7.1.26 (|err_erf| <= 1.5e-7) + fast exp
__device__ __forceinline__ float gelu_fast(float z) {
    float u = fabsf(z) * 0.70710678118654752f;
    float t = __fdividef(1.0f, fmaf(0.3275911f, u, 1.0f));
    float p =               1.061405429f;
    p = fmaf(p, t, -1.453152027f);
    p = fmaf(p, t,  1.421413741f);
    p = fmaf(p, t, -0.284496736f);
    p = fmaf(p, t,  0.254829592f);
    p = p * t;
    float erfc_u = p * __expf(-u * u);       // erfc(u), u>=0
    float erf_s  = copysignf(1.0f - erfc_u, z);
    return 0.5f * z * (1.0f + erf_s);
}

// ---------------- prep kernels ----------------
__global__ void prep_w(const float* __restrict__ W) {
    int p = blockIdx.x * 256 + threadIdx.x;            // quad index < 4096*152
    int idx = p * 4;
    int m = idx / KPAD, k = idx - m * KPAD;
    // GEMM K-index c*3+kk equals flattened W[m][c][kk] for k<600 (W row = 768 floats)
    const float* wr = W + m * 768 + k;
    float v0 = (k     < 600) ? wr[0] : 0.0f;
    float v1 = (k + 1 < 600) ? wr[1] : 0.0f;
    float v2 = (k + 2 < 600) ? wr[2] : 0.0f;
    float v3 = (k + 3 < 600) ? wr[3] : 0.0f;
    __half2 h01, h23;
    h01.x = __float2half_rn(v0); h01.y = __float2half_rn(v1);
    h23.x = __float2half_rn(v2); h23.y = __float2half_rn(v3);
    *(__half2*)&g_A[idx]     = h01;
    *(__half2*)&g_A[idx + 2] = h23;
}

__global__ void prep_x(const float* __restrict__ x) {
    __shared__ float xs[50][68];
    const int b = blockIdx.y, t0 = blockIdx.x * 64;
    const int tid = threadIdx.x;
    const float* xb = x + (size_t)b * NCH * TLEN;
    const size_t Bbase = ((size_t)b * TLEN + t0) * KPAD;

    // zero K tail [600,608)
    const __half2 z2 = { __float2half_rn(0.0f), __float2half_rn(0.0f) };
    for (int i = tid; i < 64 * 4; i += 256) {
        int tl = i >> 2, q = i & 3;
        *(__half2*)&g_B[Bbase + (size_t)tl * KPAD + 600 + q * 2] = z2;
    }

    for (int cc = 0; cc < 4; cc++) {
        const int c0 = cc * 50;
        __syncthreads();
        for (int i = tid; i < 50 * 66; i += 256) {
            int r = i / 66, col = i - r * 66;
            int gt = t0 - 1 + col;
            xs[r][col] = (gt >= 0 && gt < TLEN) ? xb[(size_t)(c0 + r) * TLEN + gt] : 0.0f;
        }
        __syncthreads();
        for (int i = tid; i < 64 * 75; i += 256) {
            int tl = i / 75, j = i - tl * 75;
            int dk0 = 2 * j;
            int cl0 = dk0 / 3,       kk0 = dk0 - cl0 * 3;
            int cl1 = (dk0 + 1) / 3, kk1 = (dk0 + 1) - cl1 * 3;
            __half2 hh;
            hh.x = __float2half_rn(xs[cl0][tl + kk0]);
            hh.y = __float2half_rn(xs[cl1][tl + kk1]);
            *(__half2*)&g_B[Bbase + (size_t)tl * KPAD + (c0 * 3 + dk0)] = hh;
        }
    }
}

// ---------------- stage copies ----------------
__device__ __forceinline__ void copy_full(uint32_t sb,
        const __half* __restrict__ A, const __half* __restrict__ B,
        int k0, int tid) {
    #pragma unroll
    for (int i = 0; i < 4; i++) {              // A: 128 rows x 8 segs
        int v = tid + i * 256;
        int row = v >> 3, seg = v & 7;
        CPASYNC16(sb + A_O + row * (RS * 2) + seg * 16,
                  A + (size_t)row * KPAD + k0 + seg * 8);
    }
    #pragma unroll
    for (int i = 0; i < 2; i++) {              // B: 64 rows x 8 segs
        int v = tid + i * 256;
        int row = v >> 3, seg = v & 7;
        CPASYNC16(sb + B_O + row * (RS * 2) + seg * 16,
                  B + (size_t)row * KPAD + k0 + seg * 8);
    }
}
// tail: 32 K -> A 128x4 segs (512) + B 64x4 segs (256)
__device__ __forceinline__ void copy_half(uint32_t sb,
        const __half* __restrict__ A, const __half* __restrict__ B,
        int k0, int tid) {
    int row = tid >> 2, seg = tid & 3;         // A rows 0..63
    CPASYNC16(sb + A_O + row * (RS * 2) + seg * 16,
              A + (size_t)row * KPAD + k0 + seg * 8);
    int row2 = row + 64;                        // A rows 64..127
    CPASYNC16(sb + A_O + row2 * (RS * 2) + seg * 16,
              A + (size_t)row2 * KPAD + k0 + seg * 8);
    if (row < 64)                               // B rows 0..63
        CPASYNC16(sb + B_O + row * (RS * 2) + seg * 16,
                  B + (size_t)row * KPAD + k0 + seg * 8);
}
__device__ __forceinline__ void copy_chunk(uint32_t sb,
        const __half* __restrict__ A, const __half* __restrict__ B,
        int c, int tid) {
    if (c < NFULL) copy_full(sb, A, B, c * KCH, tid);
    else           copy_half(sb, A, B, NFULL * KCH, tid);
}

// ---------------- main HMMA kernel ----------------
__global__ __launch_bounds__(256, 2)
void dsmain(const int* __restrict__ did_arr,
            const float* __restrict__ bias,
            float* __restrict__ out) {
    extern __shared__ __half sm[];
    const uint32_t sbase = s2u(sm);
    const int tid = threadIdx.x, wid = tid >> 5, lane = tid & 31;
    const int wm = wid >> 2, wn = wid & 3;     // warp grid 2(m,64 rows) x 4(n,16 cols)
    const int t0 = blockIdx.x * TILE_N, m0 = blockIdx.y * TILE_M, b = blockIdx.z;
    const int did = did_arr[b];

    const __half* A = g_A + (size_t)(did * MD + m0) * KPAD;
    const __half* B = g_B + ((size_t)b * TLEN + t0) * KPAD;

    uint32_t a_off[4], b_off;
    {
        int tl = lane >> 3, sub = lane & 7;
        int koff = (tl >> 1) * 8;
        int mrow = wm * 64 + (tl & 1) * 8 + sub;
        #pragma unroll
        for (int mt = 0; mt < 4; mt++)
            a_off[mt] = ((mrow + mt * 16) * RS + koff) * 2;
        int g = lane >> 3;
        int nr = wn * 16 + (lane & 7) + ((g >> 1) * 8);
        int kk = (g & 1) * 8;
        b_off = (nr * RS + kk) * 2;
    }

    float acc[4][2][4];
    #pragma unroll
    for (int i = 0; i < 4; i++)
        #pragma unroll
        for (int j = 0; j < 2; j++)
            #pragma unroll
            for (int q = 0; q < 4; q++) acc[i][j][q] = 0.0f;

    // prologue: fill stages 0,1 with chunks 0,1
    copy_chunk(sbase,               A, B, 0, tid); CP_COMMIT();
    copy_chunk(sbase + STAGE_BYTES, A, B, 1, tid); CP_COMMIT();

    int sidx = 0;
    #pragma unroll 1
    for (int c = 0; c < NCHUNK; c++) {
        if (c == NCHUNK - 1) { CP_WAIT(0); } else { CP_WAIT(1); }
        __syncthreads();   // single barrier: also fences stage (c-1)%3 reuse below

        if (c + 2 < NCHUNK) {
            copy_chunk(sbase + ((c + 2) % NSTAGE) * STAGE_BYTES, A, B, c + 2, tid);
            CP_COMMIT();
        }

        const uint32_t sb = sbase + sidx * STAGE_BYTES;
        const int nks = (c < NFULL) ? 4 : 2;
        #pragma unroll
        for (int ks = 0; ks < 4; ks++) {
            if (ks >= nks) break;
            const uint32_t kb = ks * 32;       // +16 halfs
            uint32_t bf[4], af[4][4];
            ldsm_x4(bf, sb + B_O + b_off + kb);
            #pragma unroll
            for (int mt = 0; mt < 4; mt++)
                ldsm_x4(af[mt], sb + A_O + a_off[mt] + kb);
            #pragma unroll
            for (int mt = 0; mt < 4; mt++)
                #pragma unroll
                for (int nt = 0; nt < 2; nt++)
                    mma16816h(acc[mt][nt], af[mt], &bf[nt * 2]);
        }
        sidx = (sidx == NSTAGE - 1) ? 0 : sidx + 1;
    }

    // ---- epilogue: bias + fast exact GELU ----
    const float* brow = bias + did * MD + m0 + wm * 64;
    const int rsub = lane >> 2;
    const int csub = (lane & 3) * 2;
    #pragma unroll
    for (int mt = 0; mt < 4; mt++) {
        const float bv0 = brow[mt * 16 + rsub];
        const float bv1 = brow[mt * 16 + rsub + 8];
        float* o0 = out + ((size_t)(b * MD + m0 + wm * 64 + mt * 16 + rsub)) * TLEN
                        + t0 + wn * 16 + csub;
        float* o1 = o0 + 8 * TLEN;
        #pragma unroll
        for (int nt = 0; nt < 2; nt++) {
            float2 p0, p1;
            p0.x = gelu_fast(acc[mt][nt][0] + bv0);
            p0.y = gelu_fast(acc[mt][nt][1] + bv0);
            p1.x = gelu_fast(acc[mt][nt][2] + bv1);
            p1.y = gelu_fast(acc[mt][nt][3] + bv1);
            *(float2*)(o0 + nt * 8) = p0;
            *(float2*)(o1 + nt * 8) = p1;
        }
    }
}

// ---------------- launch ----------------
extern "C" void kernel_launch(void* const* d_in, const int* in_sizes, int n_in,
                              void* d_out, int out_size) {
    const float* x    = (const float*)d_in[0];   // [32, 200, 1024]
    const int*   did  = (const int*)  d_in[1];   // [32]
    const float* W    = (const float*)d_in[2];   // [4096, 256, 3]
    const float* bias = (const float*)d_in[3];   // [4096]
    float*       out  = (float*)d_out;           // [32, 512, 1024]

    cudaFuncSetAttribute(dsmain, cudaFuncAttributeMaxDynamicSharedMemorySize, SMEM_TOTAL);

    prep_w<<<(4096 * KPAD / 4) / 256, 256>>>(W);
    prep_x<<<dim3(TLEN / 64, NB), 256>>>(x);
    dsmain<<<dim3(TLEN / TILE_N, MD / TILE_M, NB), 256, SMEM_TOTAL>>>(did, bias, out);
}

// round 10
// speedup vs baseline: 1.1328x; 1.1328x over previous
#include <cuda_runtime.h>
#include <cuda_fp16.h>
#include <math.h>
#include <stdint.h>

// ---------------- problem constants ----------------
#define NCH   200
#define TLEN  1024
#define MD    512
#define NB    32
#define KPAD  640          // 600 real (200ch*3taps) + 40 zeros = 10 uniform chunks of 64

// ---------------- tiling ----------------
#define TILE_M 128
#define TILE_N 64
#define KCH    64
#define NCHUNK (KPAD / KCH)        // 10
#define NSTAGE 3
#define RS     72                  // smem row stride in halfs (144B; LDSM conflict-free)
#define A_O    0
#define A_BYTES (128 * RS * 2)             // 18432
#define B_O    A_BYTES
#define B_BYTES (64 * RS * 2)              // 9216
#define STAGE_BYTES (A_BYTES + B_BYTES)    // 27648
#define SMEM_TOTAL  (NSTAGE * STAGE_BYTES) // 82944 -> 2 CTAs/SM

// ---------------- device scratch (bss) ----------------
__device__ __half g_A[4096 * KPAD];
__device__ __half g_B[(size_t)NB * TLEN * KPAD];

// ---------------- PTX helpers (baseline PTX, compute_103-safe) ----------------
__device__ __forceinline__ uint32_t s2u(const void* p) {
    uint32_t a;
    asm("{ .reg .u64 t; cvta.to.shared.u64 t, %1; cvt.u32.u64 %0, t; }" : "=r"(a) : "l"(p));
    return a;
}
#define CPASYNC16(dst, src) \
    asm volatile("cp.async.cg.shared.global [%0], [%1], 16;" :: "r"(dst), "l"(src) : "memory")
#define CP_COMMIT() asm volatile("cp.async.commit_group;" ::: "memory")
#define CP_WAIT(n)  asm volatile("cp.async.wait_group %0;" :: "n"(n) : "memory")

__device__ __forceinline__ void ldsm_x4(uint32_t* r, uint32_t addr) {
    asm volatile("ldmatrix.sync.aligned.m8n8.x4.shared.b16 {%0,%1,%2,%3}, [%4];"
        : "=r"(r[0]), "=r"(r[1]), "=r"(r[2]), "=r"(r[3]) : "r"(addr));
}
__device__ __forceinline__ void mma16816h(float* c, const uint32_t* a, const uint32_t* b) {
    asm volatile("mma.sync.aligned.m16n8k16.row.col.f32.f16.f16.f32 "
        "{%0,%1,%2,%3}, {%4,%5,%6,%7}, {%8,%9}, {%0,%1,%2,%3};"
        : "+f"(c[0]), "+f"(c[1]), "+f"(c[2]), "+f"(c[3])
        : "r"(a[0]), "r"(a[1]), "r"(a[2]), "r"(a[3]), "r"(b[0]), "r"(b[1]));
}

// exact-erf GELU via A&S 7.1.26 (|err_erf| <= 1.5e-7) + fast exp
__device__ __forceinline__ float gelu_fast(float z) {
    float u = fabsf(z) * 0.70710678118654752f;
    float t = __fdividef(1.0f, fmaf(0.3275911f, u, 1.0f));
    float p =               1.061405429f;
    p = fmaf(p, t, -1.453152027f);
    p = fmaf(p, t,  1.421413741f);
    p = fmaf(p, t, -0.284496736f);
    p = fmaf(p, t,  0.254829592f);
    p = p * t;
    float erfc_u = p * __expf(-u * u);       // erfc(u), u>=0
    float erf_s  = copysignf(1.0f - erfc_u, z);
    return 0.5f * z * (1.0f + erf_s);
}

// ---------------- prep kernels ----------------
__global__ void prep_w(const float* __restrict__ W) {
    int p = blockIdx.x * 256 + threadIdx.x;            // quad index < 4096*160
    int idx = p * 4;
    int m = idx / KPAD, k = idx - m * KPAD;
    // GEMM K-index c*3+kk equals flattened W[m][c][kk] for k<600 (W row = 768 floats)
    const float* wr = W + m * 768 + k;
    float v0 = (k     < 600) ? wr[0] : 0.0f;
    float v1 = (k + 1 < 600) ? wr[1] : 0.0f;
    float v2 = (k + 2 < 600) ? wr[2] : 0.0f;
    float v3 = (k + 3 < 600) ? wr[3] : 0.0f;
    __half2 h01, h23;
    h01.x = __float2half_rn(v0); h01.y = __float2half_rn(v1);
    h23.x = __float2half_rn(v2); h23.y = __float2half_rn(v3);
    *(__half2*)&g_A[idx]     = h01;
    *(__half2*)&g_A[idx + 2] = h23;
}

__global__ void prep_x(const float* __restrict__ x) {
    __shared__ float xs[50][68];
    const int b = blockIdx.y, t0 = blockIdx.x * 64;
    const int tid = threadIdx.x;
    const float* xb = x + (size_t)b * NCH * TLEN;
    const size_t Bbase = ((size_t)b * TLEN + t0) * KPAD;

    // zero K tail [600,640): 20 half2 per t
    const __half2 z2 = { __float2half_rn(0.0f), __float2half_rn(0.0f) };
    for (int i = tid; i < 64 * 20; i += 256) {
        int tl = i / 20, q = i - tl * 20;
        *(__half2*)&g_B[Bbase + (size_t)tl * KPAD + 600 + q * 2] = z2;
    }

    for (int cc = 0; cc < 4; cc++) {
        const int c0 = cc * 50;
        __syncthreads();
        for (int i = tid; i < 50 * 66; i += 256) {
            int r = i / 66, col = i - r * 66;
            int gt = t0 - 1 + col;
            xs[r][col] = (gt >= 0 && gt < TLEN) ? xb[(size_t)(c0 + r) * TLEN + gt] : 0.0f;
        }
        __syncthreads();
        // 150 K-values per t -> 75 pairs, half2 stores (c0*3 is even)
        for (int i = tid; i < 64 * 75; i += 256) {
            int tl = i / 75, j = i - tl * 75;
            int dk0 = 2 * j;
            int cl0 = dk0 / 3,       kk0 = dk0 - cl0 * 3;
            int cl1 = (dk0 + 1) / 3, kk1 = (dk0 + 1) - cl1 * 3;
            __half2 hh;
            hh.x = __float2half_rn(xs[cl0][tl + kk0]);
            hh.y = __float2half_rn(xs[cl1][tl + kk1]);
            *(__half2*)&g_B[Bbase + (size_t)tl * KPAD + (c0 * 3 + dk0)] = hh;
        }
    }
}

// ---------------- stage copy: A 128x128B + B 64x128B ----------------
__device__ __forceinline__ void copy_stage(uint32_t sb,
        const __half* __restrict__ A, const __half* __restrict__ B,
        int k0, int tid) {
    #pragma unroll
    for (int i = 0; i < 4; i++) {              // A: 1024 x 16B
        int v = tid + i * 256;
        int row = v >> 3, seg = v & 7;
        CPASYNC16(sb + A_O + row * (RS * 2) + seg * 16,
                  A + (size_t)row * KPAD + k0 + seg * 8);
    }
    #pragma unroll
    for (int i = 0; i < 2; i++) {              // B: 512 x 16B
        int v = tid + i * 256;
        int row = v >> 3, seg = v & 7;
        CPASYNC16(sb + B_O + row * (RS * 2) + seg * 16,
                  B + (size_t)row * KPAD + k0 + seg * 8);
    }
}

// ---------------- main HMMA kernel ----------------
__global__ __launch_bounds__(256, 2)
void dsmain(const int* __restrict__ did_arr,
            const float* __restrict__ bias,
            float* __restrict__ out) {
    extern __shared__ __half sm[];
    const uint32_t sbase = s2u(sm);
    const int tid = threadIdx.x, wid = tid >> 5, lane = tid & 31;
    const int wm = wid >> 2, wn = wid & 3;     // warp grid 2(m,64 rows) x 4(n,16 cols)
    const int t0 = blockIdx.x * TILE_N, m0 = blockIdx.y * TILE_M, b = blockIdx.z;
    const int did = did_arr[b];

    const __half* A = g_A + (size_t)(did * MD + m0) * KPAD;
    const __half* B = g_B + ((size_t)b * TLEN + t0) * KPAD;

    // per-lane ldmatrix byte offsets (within one stage)
    uint32_t a_off[4], b_off;
    {
        int tl = lane >> 3, sub = lane & 7;
        int koff = (tl >> 1) * 8;
        int mrow = wm * 64 + (tl & 1) * 8 + sub;
        #pragma unroll
        for (int mt = 0; mt < 4; mt++)
            a_off[mt] = ((mrow + mt * 16) * RS + koff) * 2;
        int g = lane >> 3;
        int nr = wn * 16 + (lane & 7) + ((g >> 1) * 8);
        int kk = (g & 1) * 8;
        b_off = (nr * RS + kk) * 2;
    }

    float acc[4][2][4];
    #pragma unroll
    for (int i = 0; i < 4; i++)
        #pragma unroll
        for (int j = 0; j < 2; j++)
            #pragma unroll
            for (int q = 0; q < 4; q++) acc[i][j][q] = 0.0f;

    // prologue: fill 2 stages
    copy_stage(sbase,               A, B, 0,   tid); CP_COMMIT();
    copy_stage(sbase + STAGE_BYTES, A, B, KCH, tid); CP_COMMIT();

    int sidx = 0;
    for (int c = 0; c < NCHUNK; c++) {
        if (c == NCHUNK - 1) { CP_WAIT(0); } else { CP_WAIT(1); }
        __syncthreads();   // single barrier: also fences stage (c-1)%3 reuse below

        if (c + 2 < NCHUNK) {
            copy_stage(sbase + ((c + 2) % NSTAGE) * STAGE_BYTES, A, B,
                       (c + 2) * KCH, tid);
            CP_COMMIT();
        }

        const uint32_t sb = sbase + sidx * STAGE_BYTES;
        #pragma unroll
        for (int ks = 0; ks < 4; ks++) {
            const uint32_t kb = ks * 32;       // +16 halfs
            uint32_t bf[4], af[4][4];
            ldsm_x4(bf, sb + B_O + b_off + kb);
            #pragma unroll
            for (int mt = 0; mt < 4; mt++)
                ldsm_x4(af[mt], sb + A_O + a_off[mt] + kb);
            #pragma unroll
            for (int mt = 0; mt < 4; mt++)
                #pragma unroll
                for (int nt = 0; nt < 2; nt++)
                    mma16816h(acc[mt][nt], af[mt], &bf[nt * 2]);
        }
        sidx = (sidx == NSTAGE - 1) ? 0 : sidx + 1;
    }

    // ---- epilogue: bias + fast exact GELU ----
    const float* brow = bias + did * MD + m0 + wm * 64;
    const int rsub = lane >> 2;
    const int csub = (lane & 3) * 2;
    #pragma unroll
    for (int mt = 0; mt < 4; mt++) {
        const float bv0 = brow[mt * 16 + rsub];
        const float bv1 = brow[mt * 16 + rsub + 8];
        float* o0 = out + ((size_t)(b * MD + m0 + wm * 64 + mt * 16 + rsub)) * TLEN
                        + t0 + wn * 16 + csub;
        float* o1 = o0 + 8 * TLEN;
        #pragma unroll
        for (int nt = 0; nt < 2; nt++) {
            float2 p0, p1;
            p0.x = gelu_fast(acc[mt][nt][0] + bv0);
            p0.y = gelu_fast(acc[mt][nt][1] + bv0);
            p1.x = gelu_fast(acc[mt][nt][2] + bv1);
            p1.y = gelu_fast(acc[mt][nt][3] + bv1);
            *(float2*)(o0 + nt * 8) = p0;
            *(float2*)(o1 + nt * 8) = p1;
        }
    }
}

// ---------------- launch ----------------
extern "C" void kernel_launch(void* const* d_in, const int* in_sizes, int n_in,
                              void* d_out, int out_size) {
    const float* x    = (const float*)d_in[0];   // [32, 200, 1024]
    const int*   did  = (const int*)  d_in[1];   // [32]
    const float* W    = (const float*)d_in[2];   // [4096, 256, 3]
    const float* bias = (const float*)d_in[3];   // [4096]
    float*       out  = (float*)d_out;           // [32, 512, 1024]

    cudaFuncSetAttribute(dsmain, cudaFuncAttributeMaxDynamicSharedMemorySize, SMEM_TOTAL);

    prep_w<<<(4096 * KPAD / 4) / 256, 256>>>(W);
    prep_x<<<dim3(TLEN / 64, NB), 256>>>(x);
    dsmain<<<dim3(TLEN / TILE_N, MD / TILE_M, NB), 256, SMEM_TOTAL>>>(did, bias, out);
}